// round 1
// baseline (speedup 1.0000x reference)
#include <cuda_runtime.h>

// out[b, k] = sum_{i,j} in1[b,i] * in2[b,j] * cb[k,i,j]
// B = 1048576, dims 9/9, cb = [81, 9, 9] (sparse real Wigner-3j stack).
//
// Strategy:
//  - prep_kernel builds a CSR (k-major) of cb's nonzeros into __device__ globals.
//  - tp_kernel: 1 thread = 1 batch row. Outer product P[81] staged per-thread
//    column in shared (stride 257 -> conflict-free). k-loop uses a scalar
//    accumulator; per nonzero: one broadcast LDS.64 (index+value) and one
//    conflict-free LDS.32 gather from P, then FFMA. Outputs staged in shared
//    and flushed with fully coalesced, full-sector STG (avoids 8x L2 sector
//    amplification of naive row-major per-thread stores).

#define NK      81
#define NIJ     81
#define CAP     6561      // worst-case nnz (fully dense cb)
#define TPB     256
#define STRIDE  257       // odd stride -> conflict-free columns & transpose

__device__ float2 g_meta[CAP];      // {.x = __int_as_float(i*9+j), .y = value}
__device__ int    g_rowptr[NK + 1];

__global__ void prep_kernel(const float* __restrict__ cb) {
    __shared__ int counts[NK];
    __shared__ int offs[NK + 1];
    int k = threadIdx.x;
    if (k < NK) {
        int c = 0;
#pragma unroll
        for (int ij = 0; ij < NIJ; ij++) {
            float v = cb[k * NIJ + ij];
            if (fabsf(v) > 1e-7f) c++;
        }
        counts[k] = c;
    }
    __syncthreads();
    if (k == 0) {
        int s = 0;
        for (int q = 0; q < NK; q++) { offs[q] = s; s += counts[q]; }
        offs[NK] = s;
    }
    __syncthreads();
    if (k < NK) {
        int o = offs[k];
#pragma unroll
        for (int ij = 0; ij < NIJ; ij++) {
            float v = cb[k * NIJ + ij];
            if (fabsf(v) > 1e-7f) {
                g_meta[o] = make_float2(__int_as_float(ij), v);
                o++;
            }
        }
    }
    if (k <= NK) g_rowptr[k] = offs[k];
}

__global__ void __launch_bounds__(TPB, 1) tp_kernel(
    const float* __restrict__ in1,
    const float* __restrict__ in2,
    float* __restrict__ out,
    int B)
{
    extern __shared__ float smem[];
    float*  P      = smem;                          // 81 * 257 floats
    float*  O      = smem + NIJ * STRIDE;           // 81 * 257 floats
    float2* meta   = (float2*)(smem + 2 * NIJ * STRIDE);
    int*    rowptr = (int*)(meta + CAP);

    const int t = threadIdx.x;

    // Stage CSR into shared
    const int nnz = g_rowptr[NK];
    for (int q = t; q < nnz; q += TPB) meta[q] = g_meta[q];
    if (t <= NK) rowptr[t] = g_rowptr[t];
    __syncthreads();

    const int b = blockIdx.x * TPB + t;
    float a[9], c[9];
    if (b < B) {
#pragma unroll
        for (int i = 0; i < 9; i++) a[i] = in1[b * 9 + i];
#pragma unroll
        for (int j = 0; j < 9; j++) c[j] = in2[b * 9 + j];
    } else {
#pragma unroll
        for (int i = 0; i < 9; i++) { a[i] = 0.f; c[i] = 0.f; }
    }

    // Outer product into own shared column (no cross-thread access -> no sync)
#pragma unroll
    for (int i = 0; i < 9; i++)
#pragma unroll
        for (int j = 0; j < 9; j++)
            P[(i * 9 + j) * STRIDE + t] = a[i] * c[j];

    // Sparse contraction, scalar accumulator per k
#pragma unroll 1
    for (int k = 0; k < NK; k++) {
        float acc = 0.f;
        const int n1 = rowptr[k + 1];
#pragma unroll 1
        for (int n = rowptr[k]; n < n1; n++) {
            float2 m = meta[n];                         // broadcast LDS.64
            acc = fmaf(m.y, P[__float_as_int(m.x) * STRIDE + t], acc);
        }
        O[k * STRIDE + t] = acc;
    }
    __syncthreads();

    // Coalesced transpose flush: consecutive threads -> consecutive gmem floats.
    // Shared bank = (k*257 + b_local) % 32 = (k + b_local) % 32 -> injective
    // within a warp of consecutive idx -> conflict-free.
    const long long base  = (long long)blockIdx.x * TPB * NK;
    const long long limit = (long long)B * NK;
#pragma unroll 1
    for (int r = 0; r < NK; r++) {
        int idx = r * TPB + t;
        int bl  = idx / NK;
        int kk  = idx - bl * NK;
        long long g = base + idx;
        if (g < limit) out[g] = O[kk * STRIDE + bl];
    }
}

extern "C" void kernel_launch(void* const* d_in, const int* in_sizes, int n_in,
                              void* d_out, int out_size) {
    const float* in1 = (const float*)d_in[0];
    const float* in2 = (const float*)d_in[1];
    const float* cb  = (const float*)d_in[2];
    float* out = (float*)d_out;

    const int B = in_sizes[0] / 9;

    const size_t smem_bytes =
        (size_t)(2 * NIJ * STRIDE) * sizeof(float) +   // P + O
        (size_t)CAP * sizeof(float2) +                 // meta
        (size_t)(NK + 1) * sizeof(int);                // rowptr
    // 219,352 bytes < 227 KB dynamic smem limit on sm_103a

    cudaFuncSetAttribute(tp_kernel,
                         cudaFuncAttributeMaxDynamicSharedMemorySize,
                         (int)smem_bytes);

    prep_kernel<<<1, 96>>>(cb);
    tp_kernel<<<(B + TPB - 1) / TPB, TPB, smem_bytes>>>(in1, in2, out, B);
}

// round 2
// speedup vs baseline: 1.9590x; 1.9590x over previous
#include <cuda_runtime.h>

// out[b, k] = sum_{i,j} in1[b,i] * in2[b,j] * cb[k,i,j]
// B = 1048576, dims 9/9, cb = [81, 9, 9] sparse (real Wigner-3j stack).
//
// v2: runtime CSR with pair-packed meta (float4 = 2 nnz per broadcast LDS.128),
// P[81] outer product staged per-thread-column in shared (conflict-free),
// output staged in 27-row chunks and flushed coalesced with division-free
// incremental index math. 75 KB smem -> 3 CTAs/SM (15 warps) vs v1's 1 CTA.

#define NK      81
#define NIJ     81
#define TPB     160
#define STRIDE  161      // odd -> conflict-free columns and transpose
#define CHUNK   27
#define NPH     3
#define MAXPAIR 320      // shared meta capacity (pairs); global fallback beyond

__device__ float4 g_meta4[3400];      // {off0(as int bits), v0, off1, v1}, off = ij*STRIDE
__device__ int    g_rowptr2[NK + 1];  // pair-granular row pointers

__global__ void prep_kernel(const float* __restrict__ cb) {
    __shared__ int offs[NK + 1];
    __shared__ int cnt[NK];
    int k = threadIdx.x;
    if (k < NK) {
        int c = 0;
#pragma unroll
        for (int ij = 0; ij < NIJ; ij++)
            if (fabsf(cb[k * NIJ + ij]) > 1e-7f) c++;
        cnt[k] = (c + 1) >> 1;                      // pairs, padded to even
    }
    __syncthreads();
    if (k == 0) {
        int s = 0;
        for (int q = 0; q < NK; q++) { offs[q] = s; s += cnt[q]; }
        offs[NK] = s;
    }
    __syncthreads();
    if (k < NK) {
        int o = offs[k];
        int   ph = 0; float pv = 0.f; bool have = false;
#pragma unroll
        for (int ij = 0; ij < NIJ; ij++) {
            float v = cb[k * NIJ + ij];
            if (fabsf(v) > 1e-7f) {
                if (!have) { ph = ij * STRIDE; pv = v; have = true; }
                else {
                    g_meta4[o++] = make_float4(__int_as_float(ph), pv,
                                               __int_as_float(ij * STRIDE), v);
                    have = false;
                }
            }
        }
        if (have)   // pad odd row with a harmless zero entry
            g_meta4[o++] = make_float4(__int_as_float(ph), pv,
                                       __int_as_float(0), 0.f);
    }
    if (k <= NK) g_rowptr2[k] = offs[k];
}

__global__ void __launch_bounds__(TPB) tp_kernel(
    const float* __restrict__ in1,
    const float* __restrict__ in2,
    float* __restrict__ out,
    int B)
{
    extern __shared__ float smem[];
    float*  P    = smem;                                  // NIJ * STRIDE
    float*  O    = P + NIJ * STRIDE;                      // CHUNK * STRIDE
    float4* meta = (float4*)(O + CHUNK * STRIDE);         // MAXPAIR
    int*    rp   = (int*)(meta + MAXPAIR);                // NK + 1

    const int t = threadIdx.x;
    const int npairs = g_rowptr2[NK];
    const bool in_sh = (npairs <= MAXPAIR);
    if (in_sh)
        for (int q = t; q < npairs; q += TPB) meta[q] = g_meta4[q];
    if (t <= NK) rp[t] = g_rowptr2[t];

    const int b = blockIdx.x * TPB + t;
    float a[9], c[9];
    if (b < B) {
#pragma unroll
        for (int i = 0; i < 9; i++) a[i] = __ldg(&in1[b * 9 + i]);
#pragma unroll
        for (int j = 0; j < 9; j++) c[j] = __ldg(&in2[b * 9 + j]);
    } else {
#pragma unroll
        for (int i = 0; i < 9; i++) { a[i] = 0.f; c[i] = 0.f; }
    }

    float* Pt = P + t;
#pragma unroll
    for (int i = 0; i < 9; i++)
#pragma unroll
        for (int j = 0; j < 9; j++)
            Pt[(i * 9 + j) * STRIDE] = a[i] * c[j];
    __syncthreads();

    const int limit  = B * NK;                  // 84,934,656 < 2^31
    const int gbase0 = blockIdx.x * TPB * NK;

    int r = rp[0];
#pragma unroll 1
    for (int ph = 0; ph < NPH; ph++) {
        // ---- contraction for k in [ph*CHUNK, (ph+1)*CHUNK) ----
        float* Orow = O + t;
#pragma unroll 1
        for (int kq = 0; kq < CHUNK; kq++) {
            const int r1 = rp[ph * CHUNK + kq + 1];
            float acc = 0.f;
            if (in_sh) {
#pragma unroll 1
                for (; r < r1; r++) {
                    float4 m = meta[r];                       // broadcast LDS.128
                    acc = fmaf(m.y, Pt[__float_as_int(m.x)], acc);
                    acc = fmaf(m.w, Pt[__float_as_int(m.z)], acc);
                }
            } else {
#pragma unroll 1
                for (; r < r1; r++) {
                    float4 m = g_meta4[r];
                    acc = fmaf(m.y, Pt[__float_as_int(m.x)], acc);
                    acc = fmaf(m.w, Pt[__float_as_int(m.z)], acc);
                }
            }
            *Orow = acc;                        // O[kq*STRIDE + t], own column
            Orow += STRIDE;
        }
        __syncthreads();

        // ---- coalesced flush, division-free incremental indexing ----
        // slot j = rr*TPB + t maps to (bl = j/CHUNK, kq = j%CHUNK);
        // gmem addr = gbase0 + ph*CHUNK + bl*NK + kq  (runs of 27 contiguous)
        {
            int bl = t / CHUNK;                 // one const-div, t < 160
            int kq = t - bl * CHUNK;
            int gi = bl * NK + kq;
            int si = kq * STRIDE + bl;
            const int gb = gbase0 + ph * CHUNK;
#pragma unroll
            for (int rr = 0; rr < CHUNK; rr++) {
                int g = gb + gi;
                if (g < limit) out[g] = O[si];
                // advance slot by TPB=160: bl+=5, kq+=25, wrap if kq>=27
                kq += 25;
                if (kq >= CHUNK) {
                    kq -= CHUNK;
                    gi += 5 * NK + 25 + (NK - CHUNK);          // 484
                    si += 25 * STRIDE + 5 - (CHUNK * STRIDE - 1); // -316
                } else {
                    gi += 5 * NK + 25;                          // 430
                    si += 25 * STRIDE + 5;                      // 4030
                }
            }
        }
        __syncthreads();
    }
}

extern "C" void kernel_launch(void* const* d_in, const int* in_sizes, int n_in,
                              void* d_out, int out_size) {
    const float* in1 = (const float*)d_in[0];
    const float* in2 = (const float*)d_in[1];
    const float* cb  = (const float*)d_in[2];
    float* out = (float*)d_out;

    const int B = in_sizes[0] / 9;

    const size_t smem_bytes =
        (size_t)(NIJ * STRIDE) * sizeof(float) +     // P      52,164
        (size_t)(CHUNK * STRIDE) * sizeof(float) +   // O      17,388
        (size_t)MAXPAIR * sizeof(float4) +           // meta    5,120
        (size_t)(NK + 1) * sizeof(int);              // rp        328
    // = 75,000 B -> 3 CTAs/SM

    cudaFuncSetAttribute(tp_kernel,
                         cudaFuncAttributeMaxDynamicSharedMemorySize,
                         (int)smem_bytes);

    prep_kernel<<<1, 128>>>(cb);
    tp_kernel<<<(B + TPB - 1) / TPB, TPB, smem_bytes>>>(in1, in2, out, B);
}